// round 11
// baseline (speedup 1.0000x reference)
#include <cuda_runtime.h>
#include <cuda_fp16.h>

#define BB 8
#define HH 512
#define WW 512
#define HW (HH * WW)

#define TX 32
#define TYW 8                  // 256 threads
#define PY 8
#define TILE_H (TYW * PY)      // 64
#define SW (TX + 6)            // 38
#define SH (TILE_H + 6)        // 70
#define PITCH 40               // halves per smem row (80B)
#define CPY 2848               // halves per copy; 2*CPY = 5696 B = 64 mod 128 -> bank-disjoint copies
#define NBLOCKS ((WW / TX) * (HH / TILE_H) * BB)   // 1024

__device__ unsigned long long g_pack = 0ULL;

// SIMD fp16 pair-compare mask: 0xFFFF per true lane (packed u32)
__device__ __forceinline__ unsigned gt2(unsigned a, unsigned b) {
    return __hgt2_mask(*(const __half2*)&a, *(const __half2*)&b);
}

__global__ __launch_bounds__(TX * TYW, 6)
void census_fused(const float* __restrict__ pred, const float* __restrict__ tgt,
                  float* __restrict__ out) {
    // layout: predA @0, predB @CPY (shifted by 1 elem), tgtA @2*CPY, tgtB @3*CPY
    __shared__ __align__(16) unsigned short sm[4 * CPY];
    __shared__ int wsum[TYW];

    const int b  = blockIdx.z;
    const int x0 = blockIdx.x * TX;
    const int y0 = blockIdx.y * TILE_H;
    const int tid = threadIdx.y * TX + threadIdx.x;

    const float* __restrict__ pb = pred + (size_t)b * 3 * HW;
    const float* __restrict__ tb = tgt  + (size_t)b * 3 * HW;

    // Halo load + fused RGB->gray (fp32) -> fp16, reflect padding.
    for (int idx = tid; idx < SH * SW; idx += TX * TYW) {
        int ly = idx / SW;
        int lx = idx - ly * SW;
        int gy = y0 + ly - 3;
        gy = (gy < 0) ? -gy : ((gy >= HH) ? 2 * HH - 2 - gy : gy);
        int gx = x0 + lx - 3;
        gx = (gx < 0) ? -gx : ((gx >= WW) ? 2 * WW - 2 - gx : gx);
        int off = gy * WW + gx;
        float gp = fmaf(0.299f, pb[off], fmaf(0.587f, pb[HW + off], 0.114f * pb[2 * HW + off]));
        float gt = fmaf(0.299f, tb[off], fmaf(0.587f, tb[HW + off], 0.114f * tb[2 * HW + off]));
        unsigned short hp = __half_as_ushort(__float2half_rn(gp));
        unsigned short ht = __half_as_ushort(__float2half_rn(gt));
        int ib = ly * PITCH + lx;
        sm[ib] = hp;
        sm[2 * CPY + ib] = ht;
        if (lx > 0) {                       // copyB holds logical elements 1..SW-1 at idx-1
            sm[CPY + ib - 1] = hp;
            sm[3 * CPY + ib - 1] = ht;
        }
    }
    __syncthreads();

    const int tx   = threadIdx.x;
    const int base = threadIdx.y * PY;
    const int coff = (tx & 1) * CPY;        // odd lanes use shifted copy
    const int bhx  = tx & ~1;               // aligned half-index base

    // Centers broadcast to both lanes: (c, c)
    unsigned cp2[PY], ct2[PY];
#pragma unroll
    for (int k = 0; k < PY; k++) {
        int ci = (base + k + 3) * PITCH + tx + 3;
        cp2[k] = (unsigned)sm[ci] * 0x00010001u;
        ct2[k] = (unsigned)sm[2 * CPY + ci] * 0x00010001u;
    }

    unsigned accM = 0, accA = 0;   // bit0 / bit16 count fields
#pragma unroll
    for (int r = 0; r < PY + 6; r++) {
        const int rb = (base + r) * PITCH + bhx + coff;
        unsigned vp[4], vt[4];
#pragma unroll
        for (int i = 0; i < 4; i++) {
            vp[i] = *(const unsigned*)&sm[rb + 2 * i];
            vt[i] = *(const unsigned*)&sm[2 * CPY + rb + 2 * i];
        }
#pragma unroll
        for (int k = 0; k < PY; k++) {
            const int dy = r - 3 - k;
            if (dy < -3 || dy > 3) continue;         // compile-time pruned
            unsigned x0m = (gt2(cp2[k], vp[0]) ^ gt2(ct2[k], vt[0])) & 0x00010001u;
            unsigned x1m = (gt2(cp2[k], vp[1]) ^ gt2(ct2[k], vt[1])) & 0x00010001u;
            unsigned x2m = (gt2(cp2[k], vp[2]) ^ gt2(ct2[k], vt[2])) & 0x00010001u;
            unsigned x3m = (gt2(cp2[k], vp[3]) ^ gt2(ct2[k], vt[3])) & 0x00010001u;
            accM += x0m + x1m;       // IADD3
            accM += x2m;
            accA += x3m;             // lane1 of pair 3 = dx+4 (invalid) -> hi field, discarded
            // center self-compare (dy==0, dx==0 lane) is 0 automatically
        }
    }
    int cnt = (int)(accM & 0xFFFFu) + (int)(accM >> 16) + (int)(accA & 0xFFFFu);

    // Warp + block reduction
    cnt = __reduce_add_sync(0xffffffffu, cnt);
    if (tx == 0) wsum[threadIdx.y] = cnt;
    __syncthreads();

    if (tid == 0) {
        int v = 0;
#pragma unroll
        for (int w = 0; w < TYW; w++) v += wsum[w];
        unsigned long long old =
            atomicAdd(&g_pack, (unsigned long long)v + (1ULL << 40));
        if ((old >> 40) == NBLOCKS - 1) {
            unsigned long long tot = (old & ((1ULL << 40) - 1)) + (unsigned long long)v;
            const double denom = 48.0 * (double)BB * (double)HW;  // 100663296
            out[0] = (float)((double)tot / denom);
            g_pack = 0ULL;    // reset for next graph replay
        }
    }
}

extern "C" void kernel_launch(void* const* d_in, const int* in_sizes, int n_in,
                              void* d_out, int out_size) {
    const float* pred = (const float*)d_in[0];
    const float* tgt  = (const float*)d_in[1];
    float* out = (float*)d_out;
    (void)in_sizes; (void)n_in; (void)out_size;

    dim3 bdim(TX, TYW);
    dim3 gdim(WW / TX, HH / TILE_H, BB);
    census_fused<<<gdim, bdim>>>(pred, tgt, out);
}